// round 2
// baseline (speedup 1.0000x reference)
#include <cuda_runtime.h>
#include <cstdint>
#include <cstddef>

// Problem constants (fixed shapes per reference)
#define HEADS    16
#define HD       128
#define IN_DIM   1024
#define OUT_DIM  1024
#define QKV_DIM  6144    // 3*16*128
#define MAX_B    32768   // 64*512

// Scratch: __device__ globals (allocation-free rule)
__device__ float g_qkv[(size_t)MAX_B * QKV_DIM];   // 768 MB
__device__ float g_s[(size_t)MAX_B * HD];          // 16 MB

// ---------------------------------------------------------------------------
// cp.async helpers
// ---------------------------------------------------------------------------
__device__ __forceinline__ void cp_async16(void* smem, const void* gmem) {
    uint32_t s = (uint32_t)__cvta_generic_to_shared(smem);
    asm volatile("cp.async.cg.shared.global [%0], [%1], 16;\n" :: "r"(s), "l"(gmem));
}
__device__ __forceinline__ void cp_commit() { asm volatile("cp.async.commit_group;\n" ::); }
__device__ __forceinline__ void cp_wait0()  { asm volatile("cp.async.wait_group 0;\n" ::); }
__device__ __forceinline__ void cp_wait1()  { asm volatile("cp.async.wait_group 1;\n" ::); }

__device__ __forceinline__ uint32_t f2tf(float f) {
    uint32_t u;
    asm("cvt.rna.tf32.f32 %0, %1;" : "=r"(u) : "f"(f));
    return u;
}

__device__ __forceinline__ void mma_tf32(float c[4], const uint32_t a[4], const uint32_t b[2]) {
    asm volatile(
        "mma.sync.aligned.m16n8k8.row.col.f32.tf32.tf32.f32 "
        "{%0,%1,%2,%3}, {%4,%5,%6,%7}, {%8,%9}, {%0,%1,%2,%3};\n"
        : "+f"(c[0]), "+f"(c[1]), "+f"(c[2]), "+f"(c[3])
        : "r"(a[0]), "r"(a[1]), "r"(a[2]), "r"(a[3]),
          "r"(b[0]), "r"(b[1]));
}

// ---------------------------------------------------------------------------
// Generic tf32 GEMM: C[M,N] = A[M,K] * B[K,N] + bias_scale * bias[N]
// A row-major, B row-major. M%128==0, N%128==0, K%16==0 (guaranteed here).
// CTA tile 128x128, BK=16, 8 warps (4 m x 2 n), warp tile 32x64,
// mma m16n8k8: per warp 2(m) x 8(n) mma tiles per k8 step.
// ---------------------------------------------------------------------------
#define BM 128
#define BN 128
#define BK 16
#define A_PAD 20   // 16 + 4 pad floats  (80B rows, 16B aligned, conflict-free)
#define B_PAD 136  // 128 + 8 pad floats (544B rows, 16B aligned, conflict-free)

__global__ __launch_bounds__(256) void gemm_tf32_kernel(
    const float* __restrict__ A, const float* __restrict__ B,
    const float* __restrict__ bias, float bias_scale,
    float* __restrict__ C, int M, int N, int K)
{
    __shared__ float As[2][BM][A_PAD];
    __shared__ float Bs[2][BK][B_PAD];

    const int tid  = threadIdx.x;
    const int lane = tid & 31;
    const int warp = tid >> 5;
    const int wm   = warp & 3;   // 0..3 -> 32-row warp tiles
    const int wn   = warp >> 2;  // 0..1 -> 64-col warp tiles

    const int m0 = blockIdx.y * BM;
    const int n0 = blockIdx.x * BN;

    float acc[2][8][4];
    #pragma unroll
    for (int i = 0; i < 2; i++)
        #pragma unroll
        for (int j = 0; j < 8; j++)
            #pragma unroll
            for (int r = 0; r < 4; r++) acc[i][j][r] = 0.0f;

    // per-thread load coordinates
    const int a_r  = tid >> 2;        // 0..63 (and +64)
    const int a_c  = (tid & 3) * 4;   // float4 col
    const int b_rk = tid >> 5;        // 0..7 (and +8)
    const int b_c  = (tid & 31) * 4;

    #define LOAD_TILE(buf, k0) do {                                                         \
        cp_async16(&As[buf][a_r][a_c],      A + (size_t)(m0 + a_r) * K + (k0) + a_c);       \
        cp_async16(&As[buf][a_r + 64][a_c], A + (size_t)(m0 + a_r + 64) * K + (k0) + a_c);  \
        cp_async16(&Bs[buf][b_rk][b_c],     B + (size_t)((k0) + b_rk) * N + n0 + b_c);      \
        cp_async16(&Bs[buf][b_rk + 8][b_c], B + (size_t)((k0) + b_rk + 8) * N + n0 + b_c);  \
        cp_commit();                                                                        \
    } while (0)

    LOAD_TILE(0, 0);

    const int KT = K >> 4;
    for (int kt = 0; kt < KT; kt++) {
        const int buf = kt & 1;
        if (kt + 1 < KT) { LOAD_TILE(buf ^ 1, (kt + 1) << 4); cp_wait1(); }
        else             { cp_wait0(); }
        __syncthreads();

        #pragma unroll
        for (int ks = 0; ks < BK; ks += 8) {
            uint32_t af[2][4];
            #pragma unroll
            for (int mi = 0; mi < 2; mi++) {
                const int r = wm * 32 + mi * 16 + (lane >> 2);
                const int c = ks + (lane & 3);
                af[mi][0] = f2tf(As[buf][r][c]);
                af[mi][1] = f2tf(As[buf][r + 8][c]);
                af[mi][2] = f2tf(As[buf][r][c + 4]);
                af[mi][3] = f2tf(As[buf][r + 8][c + 4]);
            }
            uint32_t bf[8][2];
            #pragma unroll
            for (int ni = 0; ni < 8; ni++) {
                const int col = wn * 64 + ni * 8 + (lane >> 2);
                bf[ni][0] = f2tf(Bs[buf][ks + (lane & 3)][col]);
                bf[ni][1] = f2tf(Bs[buf][ks + (lane & 3) + 4][col]);
            }
            #pragma unroll
            for (int mi = 0; mi < 2; mi++)
                #pragma unroll
                for (int ni = 0; ni < 8; ni++)
                    mma_tf32(acc[mi][ni], af[mi], bf[ni]);
        }
        __syncthreads();
    }
    #undef LOAD_TILE

    // Epilogue: add bias_scale * bias, store fp32
    #pragma unroll
    for (int mi = 0; mi < 2; mi++) {
        const int row = m0 + wm * 32 + mi * 16 + (lane >> 2);
        #pragma unroll
        for (int ni = 0; ni < 8; ni++) {
            const int col = n0 + wn * 64 + ni * 8 + (lane & 3) * 2;
            const float b0 = bias_scale * __ldg(&bias[col]);
            const float b1 = bias_scale * __ldg(&bias[col + 1]);
            C[(size_t)row * N + col]           = acc[mi][ni][0] + b0;
            C[(size_t)row * N + col + 1]       = acc[mi][ni][1] + b1;
            C[(size_t)(row + 8) * N + col]     = acc[mi][ni][2] + b0;
            C[(size_t)(row + 8) * N + col + 1] = acc[mi][ni][3] + b1;
        }
    }
}

// ---------------------------------------------------------------------------
// Attention + head collapse: one CTA per token.
//   score[h,g] = q_h . k_g / sqrt(128); p = softmax_g(score)
//   w[g] = sum_h p[h,g];  s[d] = sum_g w[g] * v[g,d]
// ---------------------------------------------------------------------------
__global__ __launch_bounds__(256) void attn_kernel(
    const float* __restrict__ qkv, float* __restrict__ s_out)
{
    __shared__ float sq[QKV_DIM];   // q[0:2048], k[2048:4096], v[4096:6144]
    __shared__ float sp[256];       // p[h*16+g]
    __shared__ float swg[16];       // w[g]

    const int b   = blockIdx.x;
    const int tid = threadIdx.x;

    // coalesced float4 load of q,k,v for this token
    const float4* src = (const float4*)(qkv + (size_t)b * QKV_DIM);
    float4* dst = (float4*)sq;
    #pragma unroll
    for (int i = 0; i < 6; i++) dst[tid + i * 256] = src[tid + i * 256];
    __syncthreads();

    const int h = tid >> 4, g = tid & 15, lane = tid & 31;
    const float* qh = sq + h * HD;
    const float* kg = sq + 2048 + g * HD;

    // lane-staggered dot product: conflict-free smem banks
    float dot = 0.0f;
    #pragma unroll 16
    for (int dd = 0; dd < HD; dd++) {
        const int d = (dd + lane) & (HD - 1);
        dot += qh[d] * kg[d];
    }
    float sc = dot * 0.08838834764831844f;  // 1/sqrt(128)

    // softmax over g within width-16 shuffle groups
    float mx = sc;
    #pragma unroll
    for (int off = 8; off; off >>= 1)
        mx = fmaxf(mx, __shfl_xor_sync(0xffffffffu, mx, off, 16));
    float e = __expf(sc - mx);
    float sum = e;
    #pragma unroll
    for (int off = 8; off; off >>= 1)
        sum += __shfl_xor_sync(0xffffffffu, sum, off, 16);
    sp[tid] = e / sum;
    __syncthreads();

    if (tid < 16) {
        float w = 0.0f;
        #pragma unroll
        for (int hh = 0; hh < 16; hh++) w += sp[hh * 16 + tid];
        swg[tid] = w;
    }
    __syncthreads();

    if (tid < HD) {
        const float* v = sq + 4096;
        float a = 0.0f;
        #pragma unroll
        for (int gg = 0; gg < 16; gg++) a += swg[gg] * v[gg * HD + tid];
        s_out[(size_t)b * HD + tid] = a;
    }
}

// ---------------------------------------------------------------------------
// Launch
// ---------------------------------------------------------------------------
extern "C" void kernel_launch(void* const* d_in, const int* in_sizes, int n_in,
                              void* d_out, int out_size)
{
    const float* x      = (const float*)d_in[0];   // [B, 1024]
    const float* W_pre  = (const float*)d_in[1];   // [1024, 6144]
    const float* b_pre  = (const float*)d_in[2];   // [6144]
    const float* W_proj = (const float*)d_in[3];   // [128, 1024]
    const float* b_proj = (const float*)d_in[4];   // [1024]
    float* out = (float*)d_out;

    const int M = in_sizes[0] / IN_DIM;  // 32768

    float *qkv, *s;
    cudaGetSymbolAddress((void**)&qkv, g_qkv);
    cudaGetSymbolAddress((void**)&s,   g_s);

    dim3 blk(256);

    // K1: qkv = x @ W_pre + b_pre               [M, 6144]
    gemm_tf32_kernel<<<dim3(QKV_DIM / BN, M / BM), blk>>>(
        x, W_pre, b_pre, 1.0f, qkv, M, QKV_DIM, IN_DIM);

    // K2: attention collapse -> s [M, 128]
    attn_kernel<<<M, 256>>>(qkv, s);

    // K3: out = s @ W_proj + 16 * b_proj        [M, 1024]
    gemm_tf32_kernel<<<dim3(OUT_DIM / BN, M / BM), blk>>>(
        s, W_proj, b_proj, 16.0f, out, M, OUT_DIM, HD);
}

// round 4
// speedup vs baseline: 1.6115x; 1.6115x over previous
#include <cuda_runtime.h>
#include <cuda_fp16.h>
#include <cstdint>
#include <cstddef>

#define HEADS    16
#define HD       128
#define IN_DIM   1024
#define OUT_DIM  1024
#define QKV_DIM  6144
#define MAX_B    32768

// ---------------- scratch (__device__ globals; allocation-free rule) -------
__device__ float  g_qkv [(size_t)MAX_B * QKV_DIM];   // 768 MB fp32
__device__ __half g_sh  [(size_t)MAX_B * HD];        // 8 MB   s in half
__device__ __half g_xh  [(size_t)MAX_B * IN_DIM];    // 64 MB  x in half
__device__ __half g_wth [(size_t)QKV_DIM * IN_DIM];  // 12 MB  W_pre^T  [6144,1024]
__device__ __half g_wpth[(size_t)OUT_DIM * HD];      // 256 KB W_proj^T [1024,128]

// ---------------- helpers ----------------------------------------------------
__device__ __forceinline__ void cp_async16(void* s, const void* g) {
    uint32_t a = (uint32_t)__cvta_generic_to_shared(s);
    asm volatile("cp.async.cg.shared.global [%0], [%1], 16;\n" :: "r"(a), "l"(g));
}
__device__ __forceinline__ void cp_commit() { asm volatile("cp.async.commit_group;\n" ::); }
__device__ __forceinline__ void cp_wait0()  { asm volatile("cp.async.wait_group 0;\n" ::); }
__device__ __forceinline__ void cp_wait1()  { asm volatile("cp.async.wait_group 1;\n" ::); }

__device__ __forceinline__ void mma_f16(float c[4], const uint32_t a[4], const uint32_t b[2]) {
    asm volatile(
        "mma.sync.aligned.m16n8k16.row.col.f32.f16.f16.f32 "
        "{%0,%1,%2,%3}, {%4,%5,%6,%7}, {%8,%9}, {%0,%1,%2,%3};\n"
        : "+f"(c[0]), "+f"(c[1]), "+f"(c[2]), "+f"(c[3])
        : "r"(a[0]), "r"(a[1]), "r"(a[2]), "r"(a[3]),
          "r"(b[0]), "r"(b[1]));
}

// ---------------------------------------------------------------------------
// fp16 GEMM: C[M,N](fp32) = A[M,K](half, row-major) @ Bt[N,K](half)^T
//            + bias_scale * bias[N]
// CTA tile 128x128, BK=32 (halves), 8 warps (4m x 2n), warp tile 32x64.
// smem K-major both operands, row pitch 40 halves (conflict-free frag LDS).
// ---------------------------------------------------------------------------
#define BM  128
#define BN  128
#define BK  32
#define BKP 40

__global__ void __launch_bounds__(256)
gemm_f16_kernel(const __half* __restrict__ A, const __half* __restrict__ Bt,
                const float* __restrict__ bias, float bias_scale,
                float* __restrict__ C, int M, int N, int K)
{
    __shared__ __half As[2][BM][BKP];
    __shared__ __half Bs[2][BN][BKP];

    const int tid  = threadIdx.x;
    const int lane = tid & 31;
    const int warp = tid >> 5;
    const int wm   = warp & 3;   // 4 x 32-row warp tiles
    const int wn   = warp >> 2;  // 2 x 64-col warp tiles

    const int m0 = blockIdx.y * BM;
    const int n0 = blockIdx.x * BN;

    float acc[2][8][4];
    #pragma unroll
    for (int i = 0; i < 2; i++)
        #pragma unroll
        for (int j = 0; j < 8; j++)
            #pragma unroll
            for (int r = 0; r < 4; r++) acc[i][j][r] = 0.0f;

    // loader coords: 512 16B-chunks per operand tile, 2 per thread
    const int l_row = tid >> 2;        // 0..63 (+64)
    const int l_seg = (tid & 3) * 8;   // half offset within row

    #define LOAD_TILE(buf, k0) do {                                                          \
        cp_async16(&As[buf][l_row][l_seg],      A  + (size_t)(m0 + l_row)      * K + (k0) + l_seg); \
        cp_async16(&As[buf][l_row + 64][l_seg], A  + (size_t)(m0 + l_row + 64) * K + (k0) + l_seg); \
        cp_async16(&Bs[buf][l_row][l_seg],      Bt + (size_t)(n0 + l_row)      * K + (k0) + l_seg); \
        cp_async16(&Bs[buf][l_row + 64][l_seg], Bt + (size_t)(n0 + l_row + 64) * K + (k0) + l_seg); \
        cp_commit();                                                                         \
    } while (0)

    LOAD_TILE(0, 0);
    const int KT = K / BK;
    if (KT > 1) LOAD_TILE(1, BK);

    for (int kt = 0; kt < KT; kt++) {
        const int buf = kt & 1;
        if (kt + 1 < KT) cp_wait1(); else cp_wait0();
        __syncthreads();

        #pragma unroll
        for (int ks = 0; ks < 2; ks++) {           // two k16 steps per BK=32
            const int kb = ks * 16 + (lane & 3) * 2;
            uint32_t af[2][4];
            #pragma unroll
            for (int mi = 0; mi < 2; mi++) {
                const int r = wm * 32 + mi * 16 + (lane >> 2);
                af[mi][0] = *(const uint32_t*)&As[buf][r][kb];
                af[mi][1] = *(const uint32_t*)&As[buf][r + 8][kb];
                af[mi][2] = *(const uint32_t*)&As[buf][r][kb + 8];
                af[mi][3] = *(const uint32_t*)&As[buf][r + 8][kb + 8];
            }
            uint32_t bf[8][2];
            #pragma unroll
            for (int ni = 0; ni < 8; ni++) {
                const int c = wn * 64 + ni * 8 + (lane >> 2);
                bf[ni][0] = *(const uint32_t*)&Bs[buf][c][kb];
                bf[ni][1] = *(const uint32_t*)&Bs[buf][c][kb + 8];
            }
            #pragma unroll
            for (int mi = 0; mi < 2; mi++)
                #pragma unroll
                for (int ni = 0; ni < 8; ni++)
                    mma_f16(acc[mi][ni], af[mi], bf[ni]);
        }
        __syncthreads();

        if (kt + 2 < KT) LOAD_TILE(buf, (kt + 2) * BK);
    }
    #undef LOAD_TILE

    // epilogue: add scaled bias, store fp32
    #pragma unroll
    for (int mi = 0; mi < 2; mi++) {
        const int row = m0 + wm * 32 + mi * 16 + (lane >> 2);
        #pragma unroll
        for (int ni = 0; ni < 8; ni++) {
            const int col = n0 + wn * 64 + ni * 8 + (lane & 3) * 2;
            const float b0 = bias_scale * __ldg(&bias[col]);
            const float b1 = bias_scale * __ldg(&bias[col + 1]);
            C[(size_t)row * N + col]           = acc[mi][ni][0] + b0;
            C[(size_t)row * N + col + 1]       = acc[mi][ni][1] + b1;
            C[(size_t)(row + 8) * N + col]     = acc[mi][ni][2] + b0;
            C[(size_t)(row + 8) * N + col + 1] = acc[mi][ni][3] + b1;
        }
    }
}

// ---------------- fp32 -> fp16 convert (vectorized) -------------------------
__global__ void __launch_bounds__(256)
f2h_kernel(const float* __restrict__ in, __half* __restrict__ out, int n8)
{
    for (int i = blockIdx.x * blockDim.x + threadIdx.x; i < n8; i += gridDim.x * blockDim.x) {
        const float4 v0 = ((const float4*)in)[i * 2];
        const float4 v1 = ((const float4*)in)[i * 2 + 1];
        __half2 h[4];
        h[0] = __floats2half2_rn(v0.x, v0.y);
        h[1] = __floats2half2_rn(v0.z, v0.w);
        h[2] = __floats2half2_rn(v1.x, v1.y);
        h[3] = __floats2half2_rn(v1.z, v1.w);
        ((uint4*)out)[i] = *(uint4*)h;
    }
}

// ---------------- transpose + fp16 convert: out[c*R+r] = h(in[r*C+c]) -------
__global__ void __launch_bounds__(256)
transpose_h_kernel(const float* __restrict__ in, __half* __restrict__ out, int R, int Cc)
{
    __shared__ float t[32][33];
    const int tx = threadIdx.x & 31, ty = threadIdx.x >> 5;   // 32x8
    const int bx = blockIdx.x * 32, by = blockIdx.y * 32;
    #pragma unroll
    for (int j = 0; j < 4; j++)
        t[ty + j * 8][tx] = in[(size_t)(by + ty + j * 8) * Cc + bx + tx];
    __syncthreads();
    #pragma unroll
    for (int j = 0; j < 4; j++)
        out[(size_t)(bx + ty + j * 8) * R + by + tx] = __float2half_rn(t[tx][ty + j * 8]);
}

// ---------------- attention + head collapse (one CTA / token) ---------------
__global__ void __launch_bounds__(256)
attn_kernel(const float* __restrict__ qkv, __half* __restrict__ s_out)
{
    __shared__ float sq[QKV_DIM];
    __shared__ float sp[256];
    __shared__ float swg[16];

    const int b   = blockIdx.x;
    const int tid = threadIdx.x;

    const float4* src = (const float4*)(qkv + (size_t)b * QKV_DIM);
    float4* dst = (float4*)sq;
    #pragma unroll
    for (int i = 0; i < 6; i++) dst[tid + i * 256] = src[tid + i * 256];
    __syncthreads();

    const int h = tid >> 4, g = tid & 15, lane = tid & 31;
    const float* qh = sq + h * HD;
    const float* kg = sq + 2048 + g * HD;

    float dot = 0.0f;
    #pragma unroll 16
    for (int dd = 0; dd < HD; dd++) {
        const int d = (dd + lane) & (HD - 1);
        dot += qh[d] * kg[d];
    }
    float sc = dot * 0.08838834764831844f;

    float mx = sc;
    #pragma unroll
    for (int off = 8; off; off >>= 1)
        mx = fmaxf(mx, __shfl_xor_sync(0xffffffffu, mx, off, 16));
    float e = __expf(sc - mx);
    float sum = e;
    #pragma unroll
    for (int off = 8; off; off >>= 1)
        sum += __shfl_xor_sync(0xffffffffu, sum, off, 16);
    sp[tid] = e / sum;
    __syncthreads();

    if (tid < 16) {
        float w = 0.0f;
        #pragma unroll
        for (int hh = 0; hh < 16; hh++) w += sp[hh * 16 + tid];
        swg[tid] = w;
    }
    __syncthreads();

    if (tid < HD) {
        const float* v = sq + 4096;
        float a = 0.0f;
        #pragma unroll
        for (int gg = 0; gg < 16; gg++) a += swg[gg] * v[gg * HD + tid];
        s_out[(size_t)b * HD + tid] = __float2half_rn(a);
    }
}

// ---------------- launch ------------------------------------------------------
extern "C" void kernel_launch(void* const* d_in, const int* in_sizes, int n_in,
                              void* d_out, int out_size)
{
    const float* x      = (const float*)d_in[0];
    const float* W_pre  = (const float*)d_in[1];
    const float* b_pre  = (const float*)d_in[2];
    const float* W_proj = (const float*)d_in[3];
    const float* b_proj = (const float*)d_in[4];
    float* out = (float*)d_out;

    const int M = in_sizes[0] / IN_DIM;   // 32768

    float  *qkv;
    __half *sh, *xh, *wth, *wpth;
    cudaGetSymbolAddress((void**)&qkv,  g_qkv);
    cudaGetSymbolAddress((void**)&sh,   g_sh);
    cudaGetSymbolAddress((void**)&xh,   g_xh);
    cudaGetSymbolAddress((void**)&wth,  g_wth);
    cudaGetSymbolAddress((void**)&wpth, g_wpth);

    // prep: convert x, transpose+convert weights
    f2h_kernel<<<1024, 256>>>(x, xh, M * IN_DIM / 8);
    transpose_h_kernel<<<dim3(QKV_DIM / 32, IN_DIM / 32), 256>>>(W_pre, wth, IN_DIM, QKV_DIM);
    transpose_h_kernel<<<dim3(OUT_DIM / 32, HD / 32), 256>>>(W_proj, wpth, HD, OUT_DIM);

    // K1: qkv = x @ W_pre + b_pre            [M, 6144] fp32
    gemm_f16_kernel<<<dim3(QKV_DIM / BN, M / BM), 256>>>(
        xh, wth, b_pre, 1.0f, qkv, M, QKV_DIM, IN_DIM);

    // K2: attention collapse -> s[M,128] (half)
    attn_kernel<<<M, 256>>>(qkv, sh);

    // K3: out = s @ W_proj + 16*b_proj       [M, 1024] fp32
    gemm_f16_kernel<<<dim3(OUT_DIM / BN, M / BM), 256>>>(
        sh, wpth, b_proj, 16.0f, out, M, OUT_DIM, HD);
}

// round 5
// speedup vs baseline: 1.8264x; 1.1333x over previous
#include <cuda_runtime.h>
#include <cuda_fp16.h>
#include <cstdint>
#include <cstddef>

#define HEADS    16
#define HD       128
#define IN_DIM   1024
#define OUT_DIM  1024
#define QKV_DIM  6144
#define MAX_B    32768

// ---------------- scratch (__device__ globals; allocation-free rule) -------
__device__ __half g_qkv [(size_t)MAX_B * QKV_DIM];   // 384 MB  qkv in half
__device__ __half g_sh  [(size_t)MAX_B * HD];        // 8 MB    s in half
__device__ __half g_xh  [(size_t)MAX_B * IN_DIM];    // 64 MB   x in half
__device__ __half g_wth [(size_t)QKV_DIM * IN_DIM];  // 12 MB   W_pre^T  [6144,1024]
__device__ __half g_wpth[(size_t)OUT_DIM * HD];      // 256 KB  W_proj^T [1024,128]

// ---------------- helpers ----------------------------------------------------
__device__ __forceinline__ void cp_async16(void* s, const void* g) {
    uint32_t a = (uint32_t)__cvta_generic_to_shared(s);
    asm volatile("cp.async.cg.shared.global [%0], [%1], 16;\n" :: "r"(a), "l"(g));
}
__device__ __forceinline__ void cp_commit() { asm volatile("cp.async.commit_group;\n" ::); }
__device__ __forceinline__ void cp_wait0()  { asm volatile("cp.async.wait_group 0;\n" ::); }
__device__ __forceinline__ void cp_wait1()  { asm volatile("cp.async.wait_group 1;\n" ::); }

__device__ __forceinline__ void mma_f16(float c[4], const uint32_t a[4], const uint32_t b[2]) {
    asm volatile(
        "mma.sync.aligned.m16n8k16.row.col.f32.f16.f16.f32 "
        "{%0,%1,%2,%3}, {%4,%5,%6,%7}, {%8,%9}, {%0,%1,%2,%3};\n"
        : "+f"(c[0]), "+f"(c[1]), "+f"(c[2]), "+f"(c[3])
        : "r"(a[0]), "r"(a[1]), "r"(a[2]), "r"(a[3]),
          "r"(b[0]), "r"(b[1]));
}

__device__ __forceinline__ void ldsm_x4(uint32_t r[4], const void* p) {
    uint32_t a = (uint32_t)__cvta_generic_to_shared(p);
    asm volatile("ldmatrix.sync.aligned.m8n8.x4.shared.b16 {%0,%1,%2,%3}, [%4];"
                 : "=r"(r[0]), "=r"(r[1]), "=r"(r[2]), "=r"(r[3]) : "r"(a));
}

// ---------------------------------------------------------------------------
// fp16 GEMM: C[M,N](OutT) = A[M,K](half, row-major) @ Bt[N,K](half)^T
//            + bias_scale * bias[N]
// CTA tile 128x128, BK=32, 8 warps (4m x 2n), warp tile 32x64.
// K-major smem, pitch 40 halves; fragments via ldmatrix.x4 (conflict-free).
// ---------------------------------------------------------------------------
#define BM  128
#define BN  128
#define BK  32
#define BKP 40

template <typename OutT>
__global__ void __launch_bounds__(256, 2)
gemm_f16_kernel(const __half* __restrict__ A, const __half* __restrict__ Bt,
                const float* __restrict__ bias, float bias_scale,
                OutT* __restrict__ C, int M, int N, int K)
{
    __shared__ __half As[2][BM][BKP];
    __shared__ __half Bs[2][BN][BKP];

    const int tid  = threadIdx.x;
    const int lane = tid & 31;
    const int warp = tid >> 5;
    const int wm   = warp & 3;   // 4 x 32-row warp tiles
    const int wn   = warp >> 2;  // 2 x 64-col warp tiles

    const int m0 = blockIdx.y * BM;
    const int n0 = blockIdx.x * BN;

    float acc[2][8][4];
    #pragma unroll
    for (int i = 0; i < 2; i++)
        #pragma unroll
        for (int j = 0; j < 8; j++)
            #pragma unroll
            for (int r = 0; r < 4; r++) acc[i][j][r] = 0.0f;

    // loader coords: 2 x 16B chunks per operand tile per thread
    const int l_row = tid >> 2;        // 0..63 (+64)
    const int l_seg = (tid & 3) * 8;   // half offset within row

    #define LOAD_TILE(buf, k0) do {                                                                \
        cp_async16(&As[buf][l_row][l_seg],      A  + (size_t)(m0 + l_row)      * K + (k0) + l_seg); \
        cp_async16(&As[buf][l_row + 64][l_seg], A  + (size_t)(m0 + l_row + 64) * K + (k0) + l_seg); \
        cp_async16(&Bs[buf][l_row][l_seg],      Bt + (size_t)(n0 + l_row)      * K + (k0) + l_seg); \
        cp_async16(&Bs[buf][l_row + 64][l_seg], Bt + (size_t)(n0 + l_row + 64) * K + (k0) + l_seg); \
        cp_commit();                                                                               \
    } while (0)

    LOAD_TILE(0, 0);
    const int KT = K / BK;
    if (KT > 1) LOAD_TILE(1, BK);

    // ldmatrix source coordinates
    const int a_row = wm * 32 + (lane & 15);          // + mi*16
    const int a_col = (lane >> 4) * 8;                // + ks*16
    const int b_row = wn * 64 + ((lane >> 4) << 3) + (lane & 7);  // + pi*16
    const int b_col = ((lane >> 3) & 1) * 8;          // + ks*16

    for (int kt = 0; kt < KT; kt++) {
        const int buf = kt & 1;
        if (kt + 1 < KT) cp_wait1(); else cp_wait0();
        __syncthreads();

        #pragma unroll
        for (int ks = 0; ks < 2; ks++) {
            uint32_t af[2][4];
            #pragma unroll
            for (int mi = 0; mi < 2; mi++)
                ldsm_x4(af[mi], &As[buf][a_row + mi * 16][a_col + ks * 16]);

            uint32_t bfr[4][4];   // bfr[pi] = {b[2pi][0], b[2pi][1], b[2pi+1][0], b[2pi+1][1]}
            #pragma unroll
            for (int pi = 0; pi < 4; pi++)
                ldsm_x4(bfr[pi], &Bs[buf][b_row + pi * 16][b_col + ks * 16]);

            #pragma unroll
            for (int mi = 0; mi < 2; mi++)
                #pragma unroll
                for (int ni = 0; ni < 8; ni++)
                    mma_f16(acc[mi][ni], af[mi], &bfr[ni >> 1][(ni & 1) * 2]);
        }
        __syncthreads();

        if (kt + 2 < KT) LOAD_TILE(buf, (kt + 2) * BK);
    }
    #undef LOAD_TILE

    // epilogue: add scaled bias, store
    #pragma unroll
    for (int mi = 0; mi < 2; mi++) {
        const int row = m0 + wm * 32 + mi * 16 + (lane >> 2);
        #pragma unroll
        for (int ni = 0; ni < 8; ni++) {
            const int col = n0 + wn * 64 + ni * 8 + (lane & 3) * 2;
            const float b0 = bias_scale * __ldg(&bias[col]);
            const float b1 = bias_scale * __ldg(&bias[col + 1]);
            if constexpr (sizeof(OutT) == 2) {
                *(__half2*)&C[(size_t)row * N + col] =
                    __floats2half2_rn(acc[mi][ni][0] + b0, acc[mi][ni][1] + b1);
                *(__half2*)&C[(size_t)(row + 8) * N + col] =
                    __floats2half2_rn(acc[mi][ni][2] + b0, acc[mi][ni][3] + b1);
            } else {
                C[(size_t)row * N + col]           = acc[mi][ni][0] + b0;
                C[(size_t)row * N + col + 1]       = acc[mi][ni][1] + b1;
                C[(size_t)(row + 8) * N + col]     = acc[mi][ni][2] + b0;
                C[(size_t)(row + 8) * N + col + 1] = acc[mi][ni][3] + b1;
            }
        }
    }
}

// ---------------- fp32 -> fp16 convert (vectorized) -------------------------
__global__ void __launch_bounds__(256)
f2h_kernel(const float* __restrict__ in, __half* __restrict__ out, int n8)
{
    for (int i = blockIdx.x * blockDim.x + threadIdx.x; i < n8; i += gridDim.x * blockDim.x) {
        const float4 v0 = ((const float4*)in)[i * 2];
        const float4 v1 = ((const float4*)in)[i * 2 + 1];
        __half2 h[4];
        h[0] = __floats2half2_rn(v0.x, v0.y);
        h[1] = __floats2half2_rn(v0.z, v0.w);
        h[2] = __floats2half2_rn(v1.x, v1.y);
        h[3] = __floats2half2_rn(v1.z, v1.w);
        ((uint4*)out)[i] = *(uint4*)h;
    }
}

// ---------------- transpose + fp16 convert: out[c*R+r] = h(in[r*C+c]) -------
__global__ void __launch_bounds__(256)
transpose_h_kernel(const float* __restrict__ in, __half* __restrict__ out, int R, int Cc)
{
    __shared__ float t[32][33];
    const int tx = threadIdx.x & 31, ty = threadIdx.x >> 5;   // 32x8
    const int bx = blockIdx.x * 32, by = blockIdx.y * 32;
    #pragma unroll
    for (int j = 0; j < 4; j++)
        t[ty + j * 8][tx] = in[(size_t)(by + ty + j * 8) * Cc + bx + tx];
    __syncthreads();
    #pragma unroll
    for (int j = 0; j < 4; j++)
        out[(size_t)(bx + ty + j * 8) * R + by + tx] = __float2half_rn(t[tx][ty + j * 8]);
}

// ---------------- attention + head collapse (one CTA / token) ---------------
__global__ void __launch_bounds__(256)
attn_kernel(const __half* __restrict__ qkv, __half* __restrict__ s_out)
{
    __shared__ float sq[QKV_DIM];
    __shared__ float sp[256];
    __shared__ float swg[16];

    const int b   = blockIdx.x;
    const int tid = threadIdx.x;

    // 768 x 16B chunks (8 halves each); convert to fp32 in smem
    const uint4* src = (const uint4*)(qkv + (size_t)b * QKV_DIM);
    #pragma unroll
    for (int i = 0; i < 3; i++) {
        const int c = tid + i * 256;
        uint4 u = src[c];
        const __half2* hp = (const __half2*)&u;
        #pragma unroll
        for (int j = 0; j < 4; j++) {
            float2 f = __half22float2(hp[j]);
            sq[c * 8 + j * 2]     = f.x;
            sq[c * 8 + j * 2 + 1] = f.y;
        }
    }
    __syncthreads();

    const int h = tid >> 4, g = tid & 15, lane = tid & 31;
    const float* qh = sq + h * HD;
    const float* kg = sq + 2048 + g * HD;

    float dot = 0.0f;
    #pragma unroll 16
    for (int dd = 0; dd < HD; dd++) {
        const int d = (dd + lane) & (HD - 1);
        dot += qh[d] * kg[d];
    }
    float sc = dot * 0.08838834764831844f;

    float mx = sc;
    #pragma unroll
    for (int off = 8; off; off >>= 1)
        mx = fmaxf(mx, __shfl_xor_sync(0xffffffffu, mx, off, 16));
    float e = __expf(sc - mx);
    float sum = e;
    #pragma unroll
    for (int off = 8; off; off >>= 1)
        sum += __shfl_xor_sync(0xffffffffu, sum, off, 16);
    sp[tid] = e / sum;
    __syncthreads();

    if (tid < 16) {
        float w = 0.0f;
        #pragma unroll
        for (int hh = 0; hh < 16; hh++) w += sp[hh * 16 + tid];
        swg[tid] = w;
    }
    __syncthreads();

    if (tid < HD) {
        const float* v = sq + 4096;
        float a = 0.0f;
        #pragma unroll
        for (int gg = 0; gg < 16; gg++) a += swg[gg] * v[gg * HD + tid];
        s_out[(size_t)b * HD + tid] = __float2half_rn(a);
    }
}

// ---------------- launch ------------------------------------------------------
extern "C" void kernel_launch(void* const* d_in, const int* in_sizes, int n_in,
                              void* d_out, int out_size)
{
    const float* x      = (const float*)d_in[0];
    const float* W_pre  = (const float*)d_in[1];
    const float* b_pre  = (const float*)d_in[2];
    const float* W_proj = (const float*)d_in[3];
    const float* b_proj = (const float*)d_in[4];
    float* out = (float*)d_out;

    const int M = in_sizes[0] / IN_DIM;   // 32768

    __half *qkv, *sh, *xh, *wth, *wpth;
    cudaGetSymbolAddress((void**)&qkv,  g_qkv);
    cudaGetSymbolAddress((void**)&sh,   g_sh);
    cudaGetSymbolAddress((void**)&xh,   g_xh);
    cudaGetSymbolAddress((void**)&wth,  g_wth);
    cudaGetSymbolAddress((void**)&wpth, g_wpth);

    // prep: convert x, transpose+convert weights
    f2h_kernel<<<1024, 256>>>(x, xh, M * IN_DIM / 8);
    transpose_h_kernel<<<dim3(QKV_DIM / 32, IN_DIM / 32), 256>>>(W_pre, wth, IN_DIM, QKV_DIM);
    transpose_h_kernel<<<dim3(OUT_DIM / 32, HD / 32), 256>>>(W_proj, wpth, HD, OUT_DIM);

    // K1: qkv = x @ W_pre + b_pre            [M, 6144] half
    gemm_f16_kernel<__half><<<dim3(QKV_DIM / BN, M / BM), 256>>>(
        xh, wth, b_pre, 1.0f, qkv, M, QKV_DIM, IN_DIM);

    // K2: attention collapse -> s[M,128] (half)
    attn_kernel<<<M, 256>>>(qkv, sh);

    // K3: out = s @ W_proj + 16*b_proj       [M, 1024] fp32
    gemm_f16_kernel<float><<<dim3(OUT_DIM / BN, M / BM), 256>>>(
        sh, wpth, b_proj, 16.0f, out, M, OUT_DIM, HD);
}